// round 15
// baseline (speedup 1.0000x reference)
#include <cuda_runtime.h>
#include <cuda_fp16.h>
#include <cstdint>

#define B_  16
#define T_  2048
#define E_  512
#define H_  4
#define C_  3
#define NT  (B_ * T_)   // 32768 tokens

// ---------------------------------------------------------------------------
// Scratch (static device globals — allowed)
// ---------------------------------------------------------------------------
__device__ __half g_v[(size_t)NT * E_];    // 32 MB, fp16(v)
__device__ __half g_y[(size_t)NT * E_];    // 32 MB, fp16(y = V@W^T + bias)
__device__ __half g_w[(size_t)E_ * E_];    // 512 KB, fp16(W)

__device__ __forceinline__ uint32_t smem_to_u32(const void* p) {
    uint32_t a;
    asm("{ .reg .u64 t; cvta.to.shared.u64 t, %1; cvt.u32.u64 %0, t; }" : "=r"(a) : "l"(p));
    return a;
}
__device__ __forceinline__ void cp16(uint32_t dst, const void* src) {
    asm volatile("cp.async.cg.shared.global [%0], [%1], 16;" :: "r"(dst), "l"(src));
}
__device__ __forceinline__ void ldm_x4(uint32_t* r, uint32_t addr) {
    asm volatile("ldmatrix.sync.aligned.m8n8.x4.shared.b16 {%0,%1,%2,%3}, [%4];"
                 : "=r"(r[0]), "=r"(r[1]), "=r"(r[2]), "=r"(r[3]) : "r"(addr));
}
__device__ __forceinline__ void mma_fp16(float* d, const uint32_t* a, const uint32_t* b) {
    asm volatile(
        "mma.sync.aligned.m16n8k16.row.col.f32.f16.f16.f32 "
        "{%0,%1,%2,%3}, {%4,%5,%6,%7}, {%8,%9}, {%0,%1,%2,%3};"
        : "+f"(d[0]), "+f"(d[1]), "+f"(d[2]), "+f"(d[3])
        : "r"(a[0]), "r"(a[1]), "r"(a[2]), "r"(a[3]), "r"(b[0]), "r"(b[1]));
}

// ---------------------------------------------------------------------------
// Kernel A (fused): blocks [0, NT/32)   : attn -> v (fp16), R9-proven 4-token
//                   blocks [NT/32, ...) : wconv (ffn_w -> fp16) backfill
// ---------------------------------------------------------------------------
#define ATTN_BLKS  (NT / 32)          // 1024
#define WCONV_BLKS ((E_ * E_) / 256)  // 1024

__global__ __launch_bounds__(256) void attn_kernel(const int* __restrict__ tokens,
                                                   const float* __restrict__ table,
                                                   const float* __restrict__ pos,
                                                   const float* __restrict__ W) {
    int tid = threadIdx.x;

    if (blockIdx.x >= ATTN_BLKS) {
        int i = (blockIdx.x - ATTN_BLKS) * 256 + tid;
        g_w[i] = __float2half_rn(W[i]);
        return;
    }

    __shared__ float ps[C_][E_];   // 6 KB
    for (int i = tid; i < E_ * C_; i += 256) {
        float v = pos[i] + pos[E_ * C_ + i] + pos[2 * E_ * C_ + i] + pos[3 * E_ * C_ + i];
        ps[i % 3][i / 3] = v * (1.0f / 12.0f);
    }
    __syncthreads();

    const float4* pc0 = (const float4*)ps[0];
    const float4* pc1 = (const float4*)ps[1];
    const float4* pc2 = (const float4*)ps[2];

    int warp = tid >> 5, lane = tid & 31;
    int base = blockIdx.x * 32 + warp * 4;
    int t0 = base & (T_ - 1);

    float4 x0[4], x1[4], x2[4];
    const float4 z4 = make_float4(0.f, 0.f, 0.f, 0.f);

    if (t0 >= 2) {
        const float4* rp = (const float4*)(table + (size_t)tokens[base - 2] * E_);
        #pragma unroll
        for (int j = 0; j < 4; ++j) x0[j] = rp[lane + j * 32];
    } else {
        #pragma unroll
        for (int j = 0; j < 4; ++j) x0[j] = z4;
    }
    if (t0 >= 1) {
        const float4* rp = (const float4*)(table + (size_t)tokens[base - 1] * E_);
        #pragma unroll
        for (int j = 0; j < 4; ++j) x1[j] = rp[lane + j * 32];
    } else {
        #pragma unroll
        for (int j = 0; j < 4; ++j) x1[j] = z4;
    }

    #pragma unroll
    for (int it = 0; it < 4; ++it) {
        int g = base + it;
        {
            const float4* rp = (const float4*)(table + (size_t)tokens[g] * E_);
            #pragma unroll
            for (int j = 0; j < 4; ++j) x2[j] = rp[lane + j * 32];
        }

        float s0 = 0.f, s1 = 0.f, s2 = 0.f;
        #pragma unroll
        for (int j = 0; j < 4; ++j) {
            float4 p0 = pc0[lane + j * 32];
            float4 p1 = pc1[lane + j * 32];
            float4 p2 = pc2[lane + j * 32];
            s0 += x0[j].x * p0.x + x0[j].y * p0.y + x0[j].z * p0.z + x0[j].w * p0.w;
            s1 += x1[j].x * p1.x + x1[j].y * p1.y + x1[j].z * p1.z + x1[j].w * p1.w;
            s2 += x2[j].x * p2.x + x2[j].y * p2.y + x2[j].z * p2.z + x2[j].w * p2.w;
        }
        #pragma unroll
        for (int off = 16; off > 0; off >>= 1) {
            s0 += __shfl_xor_sync(0xffffffffu, s0, off);
            s1 += __shfl_xor_sync(0xffffffffu, s1, off);
            s2 += __shfl_xor_sync(0xffffffffu, s2, off);
        }

        uint2* pv = (uint2*)(g_v + (size_t)g * E_);
        #pragma unroll
        for (int j = 0; j < 4; ++j) {
            float vx = s0 * x0[j].x + s1 * x1[j].x + s2 * x2[j].x;
            float vy = s0 * x0[j].y + s1 * x1[j].y + s2 * x2[j].y;
            float vz = s0 * x0[j].z + s1 * x1[j].z + s2 * x2[j].z;
            float vw = s0 * x0[j].w + s1 * x1[j].w + s2 * x2[j].w;
            __half2 h0 = __floats2half2_rn(vx, vy);
            __half2 h1 = __floats2half2_rn(vz, vw);
            uint2 u;
            u.x = *(uint32_t*)&h0;
            u.y = *(uint32_t*)&h1;
            pv[lane + j * 32] = u;
        }
        #pragma unroll
        for (int j = 0; j < 4; ++j) { x0[j] = x1[j]; x1[j] = x2[j]; }
    }
}

// ---------------------------------------------------------------------------
// Kernel B: persistent-A HMMA fp16 GEMM  y = V @ W^T + bias -> g_y (fp16)
// CTA owns 128 rows with FULL K=512 A resident in smem (read once).
// Loops 4 N-blocks of 128 cols; B streamed via 3-stage cp.async ring.
// 256 threads, 8 warps (warp 32x64), 64 accum regs — proven inner loop.
// ---------------------------------------------------------------------------
#define PITCH_A 1040                     // 1024B data + 16B pad (16 mod 128 offset)
#define A_SMEM  (128 * PITCH_A)          // 133120
#define PITCH   144
#define TILE_B  (128 * PITCH)            // 18432 per B stage
#define NSTG    3
#define SM_GEMM (A_SMEM + NSTG * TILE_B) // 188416 bytes

__global__ __launch_bounds__(256, 1) void gemm_kernel(const float* __restrict__ bias) {
    extern __shared__ char smem[];
    const uint32_t sb = smem_to_u32(smem);
    const uint32_t aBase = sb;
    const uint32_t bBase = sb + A_SMEM;

    const int tid  = threadIdx.x;
    const int wid  = tid >> 5, lane = tid & 31;
    const int wm   = wid >> 1;          // 0..3
    const int wn   = wid & 1;           // 0..1
    const int m0   = blockIdx.x * 128;

    const char* va = (const char*)g_v;
    const char* wb = (const char*)g_w;

    // ---- load full A tile (128 rows x 1024 B = 8192 x 16B chunks) ----
    #pragma unroll
    for (int it = 0; it < 32; ++it) {
        int i = tid + it * 256;
        int r = i >> 6, c = i & 63;
        uint32_t so = r * PITCH_A + c * 16;
        size_t ga = ((size_t)(m0 + r) * E_) * 2 + c * 16;
        cp16(aBase + so, va + ga);
    }
    asm volatile("cp.async.commit_group;" ::: "memory");

    // ---- B stage issue: j in [0,32): nb = j>>3, kb = j&7 ----
    auto issue_stage = [&](int j) {
        const uint32_t st = bBase + (j % NSTG) * TILE_B;
        const int n0 = (j >> 3) * 128;
        const int k0 = (j & 7) * 64;
        #pragma unroll
        for (int it = 0; it < 4; ++it) {
            int i = tid + it * 256;            // 0..1023
            int r = i >> 3, c = i & 7;
            uint32_t so = r * PITCH + c * 16;
            size_t gb = ((size_t)(n0 + r) * E_ + k0 + c * 8) * 2;
            cp16(st + so, wb + gb);
        }
        asm volatile("cp.async.commit_group;" ::: "memory");
    };

    const int a_row = (lane & 7) + ((lane >> 3) & 1) * 8;
    const int a_k8  = (lane >> 4);
    const int b_row = (lane & 7) + ((lane >> 4) & 1) * 8;
    const int b_k8  = (lane >> 3) & 1;
    const int g = lane >> 2, t = lane & 3;

    issue_stage(0);
    issue_stage(1);

    float d[2][8][4];

    for (int i = 0; i < 32; ++i) {
        const int kb = i & 7;
        const int nb = i >> 3;

        if (kb == 0) {
            #pragma unroll
            for (int a0 = 0; a0 < 2; ++a0)
                #pragma unroll
                for (int j = 0; j < 8; ++j)
                    #pragma unroll
                    for (int q = 0; q < 4; ++q) d[a0][j][q] = 0.0f;
        }

        if (i < 31)
            asm volatile("cp.async.wait_group 1;" ::: "memory");
        else
            asm volatile("cp.async.wait_group 0;" ::: "memory");
        __syncthreads();

        if (i + 2 < 32) issue_stage(i + 2);

        const uint32_t bT = bBase + (i % NSTG) * TILE_B;
        const int k0 = kb * 64;

        #pragma unroll
        for (int kk = 0; kk < 4; ++kk) {
            uint32_t a[2][4];
            #pragma unroll
            for (int mi = 0; mi < 2; ++mi) {
                uint32_t off = (uint32_t)(wm * 32 + mi * 16 + a_row) * PITCH_A
                             + k0 * 2 + kk * 32 + a_k8 * 16;
                ldm_x4(a[mi], aBase + off);
            }
            #pragma unroll
            for (int ni = 0; ni < 4; ++ni) {
                uint32_t off = (uint32_t)(wn * 64 + ni * 16 + b_row) * PITCH
                             + kk * 32 + b_k8 * 16;
                uint32_t bq[4];
                ldm_x4(bq, bT + off);
                #pragma unroll
                for (int mi = 0; mi < 2; ++mi) {
                    mma_fp16(d[mi][ni * 2 + 0], a[mi], bq + 0);
                    mma_fp16(d[mi][ni * 2 + 1], a[mi], bq + 2);
                }
            }
        }

        if (kb == 7) {
            // Epilogue for this n-block: + bias, fp16 quantize, write g_y
            const int n0 = nb * 128;
            #pragma unroll
            for (int mi = 0; mi < 2; ++mi) {
                #pragma unroll
                for (int ni = 0; ni < 4; ++ni) {
                    #pragma unroll
                    for (int h = 0; h < 2; ++h) {
                        int col = n0 + wn * 64 + ni * 16 + h * 8 + t * 2;
                        float b0 = __ldg(bias + col), b1 = __ldg(bias + col + 1);
                        int row = m0 + wm * 32 + mi * 16 + g;
                        const float* dd = d[mi][ni * 2 + h];
                        __half2 y0 = __floats2half2_rn(dd[0] + b0, dd[1] + b1);
                        __half2 y1 = __floats2half2_rn(dd[2] + b0, dd[3] + b1);
                        *(uint32_t*)(g_y + (size_t)row * E_ + col)       = *(uint32_t*)&y0;
                        *(uint32_t*)(g_y + (size_t)(row + 8) * E_ + col) = *(uint32_t*)&y1;
                    }
                }
            }
        }
    }
}

// ---------------------------------------------------------------------------
// Kernel C: LayerNorm + swish — R12-proven 1 row/warp + fast sigmoid.
// Reads fp16 y, writes fp32 out. 256 threads = 8 warps = 8 rows/block.
// ---------------------------------------------------------------------------
__global__ __launch_bounds__(256) void ln_kernel(const float* __restrict__ gamma,
                                                 const float* __restrict__ beta,
                                                 float* __restrict__ out) {
    int tid = threadIdx.x;
    int warp = tid >> 5, lane = tid & 31;
    int row = blockIdx.x * 8 + warp;

    const uint4* py = (const uint4*)(g_y + (size_t)row * E_);  // 64 uint4 per row
    uint4 u[2];
    #pragma unroll
    for (int j = 0; j < 2; ++j) u[j] = py[lane + j * 32];

    float y[16];
    #pragma unroll
    for (int j = 0; j < 2; ++j) {
        const uint32_t* uu = (const uint32_t*)&u[j];
        #pragma unroll
        for (int q = 0; q < 4; ++q) {
            float2 f = __half22float2(*(const __half2*)&uu[q]);
            y[j * 8 + q * 2 + 0] = f.x;
            y[j * 8 + q * 2 + 1] = f.y;
        }
    }

    float sum = 0.f, sq = 0.f;
    #pragma unroll
    for (int i = 0; i < 16; ++i) { sum += y[i]; sq += y[i] * y[i]; }
    #pragma unroll
    for (int off = 16; off > 0; off >>= 1) {
        sum += __shfl_xor_sync(0xffffffffu, sum, off);
        sq  += __shfl_xor_sync(0xffffffffu, sq,  off);
    }

    float mean = sum * (1.0f / E_);
    float var  = sq * (1.0f / E_) - mean * mean;
    float rstd = rsqrtf(var + 1e-5f);

    float* op = out + (size_t)row * E_;
    #pragma unroll
    for (int j = 0; j < 2; ++j) {
        int c0 = lane * 8 + j * 256;
        #pragma unroll
        for (int q2 = 0; q2 < 2; ++q2) {
            float4 gm = *(const float4*)(gamma + c0 + q2 * 4);
            float4 bt = *(const float4*)(beta  + c0 + q2 * 4);
            const float* yy = &y[j * 8 + q2 * 4];
            float4 o;
            float* po = &o.x;
            const float* gg = &gm.x; const float* bb = &bt.x;
            #pragma unroll
            for (int q = 0; q < 4; ++q) {
                float a = (yy[q] - mean) * rstd * gg[q] + bb[q];
                po[q] = __fdividef(a, 1.0f + __expf(-a));
            }
            *(float4*)(op + c0 + q2 * 4) = o;
        }
    }
}

// ---------------------------------------------------------------------------
extern "C" void kernel_launch(void* const* d_in, const int* in_sizes, int n_in,
                              void* d_out, int out_size) {
    const int*   tokens = (const int*)  d_in[0];
    const float* table  = (const float*)d_in[1];
    const float* pos    = (const float*)d_in[2];
    const float* ffn_w  = (const float*)d_in[3];
    const float* ffn_b  = (const float*)d_in[4];
    const float* ln_g   = (const float*)d_in[5];
    const float* ln_b   = (const float*)d_in[6];
    float* out = (float*)d_out;

    cudaFuncSetAttribute(gemm_kernel, cudaFuncAttributeMaxDynamicSharedMemorySize, SM_GEMM);

    attn_kernel<<<ATTN_BLKS + WCONV_BLKS, 256>>>(tokens, table, pos, ffn_w);
    gemm_kernel<<<NT / 128, 256, SM_GEMM>>>(ffn_b);
    ln_kernel<<<NT / 8, 256>>>(ln_g, ln_b, out);
}

// round 16
// speedup vs baseline: 1.1525x; 1.1525x over previous
#include <cuda_runtime.h>
#include <cuda_fp16.h>
#include <cstdint>

#define B_  16
#define T_  2048
#define E_  512
#define H_  4
#define C_  3
#define NT  (B_ * T_)   // 32768 tokens

// ---------------------------------------------------------------------------
// Scratch (static device globals — allowed)
// ---------------------------------------------------------------------------
__device__ __half g_v[(size_t)NT * E_];    // 32 MB, fp16(v)
__device__ __half g_y[(size_t)NT * E_];    // 32 MB, fp16(y = V@W^T + bias)
__device__ __half g_w[(size_t)E_ * E_];    // 512 KB, fp16(W)

__device__ __forceinline__ uint32_t smem_to_u32(const void* p) {
    uint32_t a;
    asm("{ .reg .u64 t; cvta.to.shared.u64 t, %1; cvt.u32.u64 %0, t; }" : "=r"(a) : "l"(p));
    return a;
}
__device__ __forceinline__ void cp16(uint32_t dst, const void* src) {
    asm volatile("cp.async.cg.shared.global [%0], [%1], 16;" :: "r"(dst), "l"(src));
}
__device__ __forceinline__ void ldm_x4(uint32_t* r, uint32_t addr) {
    asm volatile("ldmatrix.sync.aligned.m8n8.x4.shared.b16 {%0,%1,%2,%3}, [%4];"
                 : "=r"(r[0]), "=r"(r[1]), "=r"(r[2]), "=r"(r[3]) : "r"(addr));
}
__device__ __forceinline__ void mma_fp16(float* d, const uint32_t* a, const uint32_t* b) {
    asm volatile(
        "mma.sync.aligned.m16n8k16.row.col.f32.f16.f16.f32 "
        "{%0,%1,%2,%3}, {%4,%5,%6,%7}, {%8,%9}, {%0,%1,%2,%3};"
        : "+f"(d[0]), "+f"(d[1]), "+f"(d[2]), "+f"(d[3])
        : "r"(a[0]), "r"(a[1]), "r"(a[2]), "r"(a[3]), "r"(b[0]), "r"(b[1]));
}
__device__ __forceinline__ void stg_cs_128(float* p, float4 v) {
    asm volatile("st.global.cs.v4.f32 [%0], {%1,%2,%3,%4};"
                 :: "l"(p), "f"(v.x), "f"(v.y), "f"(v.z), "f"(v.w) : "memory");
}

// ---------------------------------------------------------------------------
// Kernel A (fused): blocks [0, NT/32)   : attn -> v (fp16), R9-proven 4-token
//                   blocks [NT/32, ...) : wconv (ffn_w -> fp16) backfill
// ---------------------------------------------------------------------------
#define ATTN_BLKS  (NT / 32)          // 1024
#define WCONV_BLKS ((E_ * E_) / 256)  // 1024

__global__ __launch_bounds__(256) void attn_kernel(const int* __restrict__ tokens,
                                                   const float* __restrict__ table,
                                                   const float* __restrict__ pos,
                                                   const float* __restrict__ W) {
    int tid = threadIdx.x;

    if (blockIdx.x >= ATTN_BLKS) {
        int i = (blockIdx.x - ATTN_BLKS) * 256 + tid;
        g_w[i] = __float2half_rn(W[i]);
        return;
    }

    __shared__ float ps[C_][E_];   // 6 KB
    for (int i = tid; i < E_ * C_; i += 256) {
        float v = pos[i] + pos[E_ * C_ + i] + pos[2 * E_ * C_ + i] + pos[3 * E_ * C_ + i];
        ps[i % 3][i / 3] = v * (1.0f / 12.0f);
    }
    __syncthreads();

    const float4* pc0 = (const float4*)ps[0];
    const float4* pc1 = (const float4*)ps[1];
    const float4* pc2 = (const float4*)ps[2];

    int warp = tid >> 5, lane = tid & 31;
    int base = blockIdx.x * 32 + warp * 4;
    int t0 = base & (T_ - 1);

    float4 x0[4], x1[4], x2[4];
    const float4 z4 = make_float4(0.f, 0.f, 0.f, 0.f);

    if (t0 >= 2) {
        const float4* rp = (const float4*)(table + (size_t)tokens[base - 2] * E_);
        #pragma unroll
        for (int j = 0; j < 4; ++j) x0[j] = rp[lane + j * 32];
    } else {
        #pragma unroll
        for (int j = 0; j < 4; ++j) x0[j] = z4;
    }
    if (t0 >= 1) {
        const float4* rp = (const float4*)(table + (size_t)tokens[base - 1] * E_);
        #pragma unroll
        for (int j = 0; j < 4; ++j) x1[j] = rp[lane + j * 32];
    } else {
        #pragma unroll
        for (int j = 0; j < 4; ++j) x1[j] = z4;
    }

    #pragma unroll
    for (int it = 0; it < 4; ++it) {
        int g = base + it;
        {
            const float4* rp = (const float4*)(table + (size_t)tokens[g] * E_);
            #pragma unroll
            for (int j = 0; j < 4; ++j) x2[j] = rp[lane + j * 32];
        }

        float s0 = 0.f, s1 = 0.f, s2 = 0.f;
        #pragma unroll
        for (int j = 0; j < 4; ++j) {
            float4 p0 = pc0[lane + j * 32];
            float4 p1 = pc1[lane + j * 32];
            float4 p2 = pc2[lane + j * 32];
            s0 += x0[j].x * p0.x + x0[j].y * p0.y + x0[j].z * p0.z + x0[j].w * p0.w;
            s1 += x1[j].x * p1.x + x1[j].y * p1.y + x1[j].z * p1.z + x1[j].w * p1.w;
            s2 += x2[j].x * p2.x + x2[j].y * p2.y + x2[j].z * p2.z + x2[j].w * p2.w;
        }
        #pragma unroll
        for (int off = 16; off > 0; off >>= 1) {
            s0 += __shfl_xor_sync(0xffffffffu, s0, off);
            s1 += __shfl_xor_sync(0xffffffffu, s1, off);
            s2 += __shfl_xor_sync(0xffffffffu, s2, off);
        }

        uint2* pv = (uint2*)(g_v + (size_t)g * E_);
        #pragma unroll
        for (int j = 0; j < 4; ++j) {
            float vx = s0 * x0[j].x + s1 * x1[j].x + s2 * x2[j].x;
            float vy = s0 * x0[j].y + s1 * x1[j].y + s2 * x2[j].y;
            float vz = s0 * x0[j].z + s1 * x1[j].z + s2 * x2[j].z;
            float vw = s0 * x0[j].w + s1 * x1[j].w + s2 * x2[j].w;
            __half2 h0 = __floats2half2_rn(vx, vy);
            __half2 h1 = __floats2half2_rn(vz, vw);
            uint2 u;
            u.x = *(uint32_t*)&h0;
            u.y = *(uint32_t*)&h1;
            pv[lane + j * 32] = u;
        }
        #pragma unroll
        for (int j = 0; j < 4; ++j) { x0[j] = x1[j]; x1[j] = x2[j]; }
    }
}

// ---------------------------------------------------------------------------
// Kernel B: HMMA fp16 GEMM  y = V @ W^T + bias -> g_y (fp16)
// R12/R14-proven: CTA 128x128, KBLK=64, 8 warps (32x64), 3-stage, 2 CTAs/SM.
// ---------------------------------------------------------------------------
#define KBLK   64
#define PITCH  144
#define TILE_B (128 * PITCH)            // 18432 bytes per operand tile
#define STAGE  (2 * TILE_B)             // A, B = 36864
#define NSTG   3
#define SM_GEMM (NSTG * STAGE)          // 110592 bytes

__global__ __launch_bounds__(256, 2) void gemm_kernel(const float* __restrict__ bias) {
    extern __shared__ char smem[];
    const uint32_t sb = smem_to_u32(smem);

    const int tid  = threadIdx.x;
    const int wid  = tid >> 5, lane = tid & 31;
    const int wm   = wid >> 1;          // 0..3
    const int wn   = wid & 1;           // 0..1
    const int m0   = blockIdx.y * 128;
    const int n0   = blockIdx.x * 128;

    const char* va = (const char*)g_v;
    const char* wb = (const char*)g_w;

    auto issue_stage = [&](int kb) {
        const uint32_t st = sb + (kb % NSTG) * STAGE;
        const int k0 = kb * KBLK;
        #pragma unroll
        for (int it = 0; it < 4; ++it) {
            int i = tid + it * 256;            // 0..1023
            int r = i >> 3, c = i & 7;
            uint32_t so = r * PITCH + c * 16;
            size_t ga = ((size_t)(m0 + r) * E_ + k0 + c * 8) * 2;
            size_t gb = ((size_t)(n0 + r) * E_ + k0 + c * 8) * 2;
            cp16(st + 0 * TILE_B + so, va + ga);
            cp16(st + 1 * TILE_B + so, wb + gb);
        }
        asm volatile("cp.async.commit_group;" ::: "memory");
    };

    float d[2][8][4];
    #pragma unroll
    for (int i = 0; i < 2; ++i)
        #pragma unroll
        for (int j = 0; j < 8; ++j)
            #pragma unroll
            for (int q = 0; q < 4; ++q) d[i][j][q] = 0.0f;

    const int a_row = (lane & 7) + ((lane >> 3) & 1) * 8;
    const int a_k8  = (lane >> 4);
    const int b_row = (lane & 7) + ((lane >> 4) & 1) * 8;
    const int b_k8  = (lane >> 3) & 1;

    issue_stage(0);
    issue_stage(1);

    const int NKB = E_ / KBLK;   // 8
    for (int kb = 0; kb < NKB; ++kb) {
        if (kb < NKB - 1)
            asm volatile("cp.async.wait_group 1;" ::: "memory");
        else
            asm volatile("cp.async.wait_group 0;" ::: "memory");
        __syncthreads();

        // safe: buffer (kb+2)%3 == (kb-1)%3, all its readers passed the barrier
        if (kb + 2 < NKB) issue_stage(kb + 2);

        const uint32_t st = sb + (kb % NSTG) * STAGE;
        const uint32_t aT = st + 0 * TILE_B;
        const uint32_t bT = st + 1 * TILE_B;

        #pragma unroll
        for (int kk = 0; kk < 4; ++kk) {
            uint32_t a[2][4];
            #pragma unroll
            for (int mi = 0; mi < 2; ++mi) {
                uint32_t off = (uint32_t)(wm * 32 + mi * 16 + a_row) * PITCH
                             + kk * 32 + a_k8 * 16;
                ldm_x4(a[mi], aT + off);
            }
            #pragma unroll
            for (int ni = 0; ni < 4; ++ni) {
                uint32_t off = (uint32_t)(wn * 64 + ni * 16 + b_row) * PITCH
                             + kk * 32 + b_k8 * 16;
                uint32_t bq[4];
                ldm_x4(bq, bT + off);
                #pragma unroll
                for (int mi = 0; mi < 2; ++mi) {
                    mma_fp16(d[mi][ni * 2 + 0], a[mi], bq + 0);
                    mma_fp16(d[mi][ni * 2 + 1], a[mi], bq + 2);
                }
            }
        }
    }

    // Epilogue: + bias, quantize fp16, write g_y (kept L2-resident for ln)
    const int g = lane >> 2, t = lane & 3;
    #pragma unroll
    for (int mi = 0; mi < 2; ++mi) {
        #pragma unroll
        for (int ni = 0; ni < 4; ++ni) {
            #pragma unroll
            for (int h = 0; h < 2; ++h) {
                int col = n0 + wn * 64 + ni * 16 + h * 8 + t * 2;
                float b0 = __ldg(bias + col), b1 = __ldg(bias + col + 1);
                int row = m0 + wm * 32 + mi * 16 + g;
                const float* dd = d[mi][ni * 2 + h];
                __half2 y0 = __floats2half2_rn(dd[0] + b0, dd[1] + b1);
                __half2 y1 = __floats2half2_rn(dd[2] + b0, dd[3] + b1);
                *(uint32_t*)(g_y + (size_t)row * E_ + col)       = *(uint32_t*)&y0;
                *(uint32_t*)(g_y + (size_t)(row + 8) * E_ + col) = *(uint32_t*)&y1;
            }
        }
    }
}

// ---------------------------------------------------------------------------
// Kernel C: LayerNorm + swish — R12-proven 1 row/warp + fast sigmoid.
// Reads fp16 y (L2-hot), writes fp32 out with .cs (streamed, never re-read).
// ---------------------------------------------------------------------------
__global__ __launch_bounds__(256) void ln_kernel(const float* __restrict__ gamma,
                                                 const float* __restrict__ beta,
                                                 float* __restrict__ out) {
    int tid = threadIdx.x;
    int warp = tid >> 5, lane = tid & 31;
    int row = blockIdx.x * 8 + warp;

    const uint4* py = (const uint4*)(g_y + (size_t)row * E_);  // 64 uint4 per row
    uint4 u[2];
    #pragma unroll
    for (int j = 0; j < 2; ++j) u[j] = py[lane + j * 32];

    float y[16];
    #pragma unroll
    for (int j = 0; j < 2; ++j) {
        const uint32_t* uu = (const uint32_t*)&u[j];
        #pragma unroll
        for (int q = 0; q < 4; ++q) {
            float2 f = __half22float2(*(const __half2*)&uu[q]);
            y[j * 8 + q * 2 + 0] = f.x;
            y[j * 8 + q * 2 + 1] = f.y;
        }
    }

    float sum = 0.f, sq = 0.f;
    #pragma unroll
    for (int i = 0; i < 16; ++i) { sum += y[i]; sq += y[i] * y[i]; }
    #pragma unroll
    for (int off = 16; off > 0; off >>= 1) {
        sum += __shfl_xor_sync(0xffffffffu, sum, off);
        sq  += __shfl_xor_sync(0xffffffffu, sq,  off);
    }

    float mean = sum * (1.0f / E_);
    float var  = sq * (1.0f / E_) - mean * mean;
    float rstd = rsqrtf(var + 1e-5f);

    float* op = out + (size_t)row * E_;
    #pragma unroll
    for (int j = 0; j < 2; ++j) {
        int c0 = lane * 8 + j * 256;
        #pragma unroll
        for (int q2 = 0; q2 < 2; ++q2) {
            float4 gm = *(const float4*)(gamma + c0 + q2 * 4);
            float4 bt = *(const float4*)(beta  + c0 + q2 * 4);
            const float* yy = &y[j * 8 + q2 * 4];
            float4 o;
            float* po = &o.x;
            const float* gg = &gm.x; const float* bb = &bt.x;
            #pragma unroll
            for (int q = 0; q < 4; ++q) {
                float a = (yy[q] - mean) * rstd * gg[q] + bb[q];
                po[q] = __fdividef(a, 1.0f + __expf(-a));
            }
            stg_cs_128(op + c0 + q2 * 4, o);
        }
    }
}

// ---------------------------------------------------------------------------
extern "C" void kernel_launch(void* const* d_in, const int* in_sizes, int n_in,
                              void* d_out, int out_size) {
    const int*   tokens = (const int*)  d_in[0];
    const float* table  = (const float*)d_in[1];
    const float* pos    = (const float*)d_in[2];
    const float* ffn_w  = (const float*)d_in[3];
    const float* ffn_b  = (const float*)d_in[4];
    const float* ln_g   = (const float*)d_in[5];
    const float* ln_b   = (const float*)d_in[6];
    float* out = (float*)d_out;

    cudaFuncSetAttribute(gemm_kernel, cudaFuncAttributeMaxDynamicSharedMemorySize, SM_GEMM);

    attn_kernel<<<ATTN_BLKS + WCONV_BLKS, 256>>>(tokens, table, pos, ffn_w);
    dim3 gg(E_ / 128, NT / 128);   // (4, 256)
    gemm_kernel<<<gg, 256, SM_GEMM>>>(ffn_b);
    ln_kernel<<<NT / 8, 256>>>(ln_g, ln_b, out);
}